// round 16
// baseline (speedup 1.0000x reference)
#include <cuda_runtime.h>
#include <cuda_fp16.h>

#define D 128
#define MAX_N 100000
#define MBLK 64            // rows of x per GEMM block
#define PADH 136           // GEMM smem row stride in halves

// scatter tile constants
#define TILE_E 128                     // edges per tile
#define SPAD 136                       // S/A row stride in halves
#define S_BYTES (TILE_E * SPAD * 2)    // 34816
#define A_BYTES (16 * SPAD * 2)        // 4352
#define SRC_BYTES (TILE_E * 4)         // 512
#define SCAT_SMEM (S_BYTES + A_BYTES + SRC_BYTES)   // 39680

// support = x@W + b, stored fp16 (25.6 MB)
__device__ __half g_support_h[(size_t)MAX_N * D];
// W transposed + converted to fp16: Wt[n][k]
__device__ __half g_Wt_h[D * D];
// CSR row pointers for destination nodes
__device__ int g_rowptr[MAX_N + 1];

// ---------------------------------------------------------------------------
// prep: Wt_h[n][k] = fp16(W[k][n])
// ---------------------------------------------------------------------------
__global__ void prep_kernel(const float* __restrict__ W, __half* __restrict__ Wt) {
    int i = blockIdx.x * blockDim.x + threadIdx.x;
    if (i < D * D) {
        int k = i >> 7, n = i & 127;
        Wt[n * D + k] = __float2half(W[i]);
    }
}

// ---------------------------------------------------------------------------
// rowptr: edst sorted -> rp[d] = first edge with dst >= d. O(E+N).
// ---------------------------------------------------------------------------
__global__ void rowptr_kernel(const int* __restrict__ edst,
                              int* __restrict__ rp, int E, int N) {
    int e = blockIdx.x * blockDim.x + threadIdx.x;
    if (e >= E) return;
    int d  = edst[e];
    int dp = (e == 0) ? -1 : edst[e - 1];
    for (int k = dp + 1; k <= d; k++) rp[k] = e;
    if (e == E - 1)
        for (int k = d + 1; k <= N; k++) rp[k] = E;
}

__device__ __forceinline__ void mma_f16(float d[4], unsigned a0, unsigned a1,
                                        unsigned a2, unsigned a3,
                                        unsigned b0, unsigned b1) {
    asm volatile(
        "mma.sync.aligned.m16n8k16.row.col.f32.f16.f16.f32 "
        "{%0,%1,%2,%3}, {%4,%5,%6,%7}, {%8,%9}, {%0,%1,%2,%3};"
        : "+f"(d[0]), "+f"(d[1]), "+f"(d[2]), "+f"(d[3])
        : "r"(a0), "r"(a1), "r"(a2), "r"(a3), "r"(b0), "r"(b1));
}

__device__ __forceinline__ void ldsm_x4_trans(unsigned& r0, unsigned& r1,
                                              unsigned& r2, unsigned& r3,
                                              unsigned addr) {
    asm volatile(
        "ldmatrix.sync.aligned.m8n8.x4.trans.shared.b16 {%0,%1,%2,%3}, [%4];"
        : "=r"(r0), "=r"(r1), "=r"(r2), "=r"(r3) : "r"(addr));
}

// ---------------------------------------------------------------------------
// GEMM: support = fp16(x@W + b) via fp16 mma m16n8k16. (Proven champion.)
// ---------------------------------------------------------------------------
__global__ void __launch_bounds__(256) gemm_mma_kernel(
        const float* __restrict__ x,
        const __half* __restrict__ Wt,
        const float* __restrict__ b,
        __half* __restrict__ sup, int N) {
    extern __shared__ __half smem[];
    __half* sX = smem;                 // 64  x PADH halves
    __half* sW = smem + MBLK * PADH;   // 128 x PADH halves ([n][k])

    const int tid  = threadIdx.x;
    const int lane = tid & 31;
    const int w    = tid >> 5;
    const int wm   = w & 3;
    const int wn   = w >> 2;
    const int g    = lane >> 2;
    const int tig  = lane & 3;

    const int row0 = blockIdx.x * MBLK;

    const uint4* Wv = (const uint4*)Wt;
    #pragma unroll
    for (int i = tid; i < 128 * 16; i += 256) {
        int r = i >> 4, c = i & 15;
        *(uint4*)(sW + r * PADH + c * 8) = Wv[i];
    }
    const float4* xv = (const float4*)x;
    #pragma unroll
    for (int i = tid; i < MBLK * 32; i += 256) {
        int r = i >> 5, c = i & 31;
        float4 v = make_float4(0.f, 0.f, 0.f, 0.f);
        if (row0 + r < N) v = xv[(size_t)(row0 + r) * 32 + c];
        __half2 h0 = __floats2half2_rn(v.x, v.y);
        __half2 h1 = __floats2half2_rn(v.z, v.w);
        uint2 p = make_uint2(*(unsigned*)&h0, *(unsigned*)&h1);
        *(uint2*)(sX + r * PADH + c * 4) = p;
    }
    __syncthreads();

    float acc[8][4];
    #pragma unroll
    for (int t = 0; t < 8; t++)
        #pragma unroll
        for (int j = 0; j < 4; j++) acc[t][j] = 0.f;

    const int ar0 = wm * 16 + g;
    const int ar1 = ar0 + 8;

    #pragma unroll
    for (int k0 = 0; k0 < D; k0 += 16) {
        unsigned a0 = *(const unsigned*)(sX + ar0 * PADH + k0 + 2 * tig);
        unsigned a1 = *(const unsigned*)(sX + ar1 * PADH + k0 + 2 * tig);
        unsigned a2 = *(const unsigned*)(sX + ar0 * PADH + k0 + 2 * tig + 8);
        unsigned a3 = *(const unsigned*)(sX + ar1 * PADH + k0 + 2 * tig + 8);
        #pragma unroll
        for (int t = 0; t < 8; t++) {
            int n0 = wn * 64 + t * 8;
            unsigned b0 = *(const unsigned*)(sW + (n0 + g) * PADH + k0 + 2 * tig);
            unsigned b1 = *(const unsigned*)(sW + (n0 + g) * PADH + k0 + 2 * tig + 8);
            mma_f16(acc[t], a0, a1, a2, a3, b0, b1);
        }
    }

    const int gr0 = row0 + wm * 16 + g;
    const int gr1 = gr0 + 8;
    #pragma unroll
    for (int t = 0; t < 8; t++) {
        int col = wn * 64 + t * 8 + 2 * tig;
        float bx = b[col], by = b[col + 1];
        if (gr0 < N) {
            __half2 h = __floats2half2_rn(acc[t][0] + bx, acc[t][1] + by);
            *(__half2*)(sup + (size_t)gr0 * D + col) = h;
        }
        if (gr1 < N) {
            __half2 h = __floats2half2_rn(acc[t][2] + bx, acc[t][3] + by);
            *(__half2*)(sup + (size_t)gr1 * D + col) = h;
        }
    }
}

// ---------------------------------------------------------------------------
// Tensor SpMM aggregation v2. One BLOCK (8 warps) = one 16-node group; edges
// contiguous (edst sorted). Per 128-edge tile:
//   phase 1 (all 256 threads): metadata + A[16][128] build + gather 128
//           support rows into S[128][.] (LDG.128 + STS.128)
//   phase 2 (warp w): acc(16x16 slice, cols w*16..) += A @ S via
//           direct-LDS a-frags + ldmatrix.x4.trans b-frags  (all mappings
//           proven correct in R13)
// 39.7 KB smem -> 5 blocks/SM; inter-block overlap hides gather latency.
// No atomics; every out row written exactly once.
// ---------------------------------------------------------------------------
__global__ void __launch_bounds__(256) scatter_mma_kernel(
        const __half* __restrict__ sup,
        const float* __restrict__ ew,
        const int* __restrict__ esrc,
        const int* __restrict__ edst,
        const int* __restrict__ rp,
        float* __restrict__ out, int N) {
    extern __shared__ char sm_raw[];
    __half* Smem = (__half*)sm_raw;                       // [128][SPAD]
    __half* Amem = (__half*)(sm_raw + S_BYTES);           // [16][SPAD]
    int*    sSrc = (int*)(sm_raw + S_BYTES + A_BYTES);    // [128]

    const int tid  = threadIdx.x;
    const int wid  = tid >> 5;
    const int lane = tid & 31;

    const int base_node = blockIdx.x * 16;
    const int hi_node   = min(base_node + 16, N);
    const int e0 = rp[base_node];
    const int e1 = rp[hi_node];

    const int g   = lane >> 2;      // 0..7
    const int tig = lane & 3;       // 0..3

    float acc[2][4];
    #pragma unroll
    for (int t = 0; t < 2; t++)
        #pragma unroll
        for (int j = 0; j < 4; j++) acc[t][j] = 0.f;

    const uint4* supv = (const uint4*)sup;
    const unsigned Sbase_u32 = (unsigned)__cvta_generic_to_shared(Smem);
    const int n0 = wid * 16;                       // this warp's column slice
    const int krow_off = lane & 15;
    const int ncol_off = (lane >> 4) << 3;

    for (int t0 = e0; t0 < e1; t0 += TILE_E) {
        const int tlen = min(TILE_E, e1 - t0);

        __syncthreads();   // prev tile's MMA reads complete before overwrite

        // zero A (272 uint4 over 256 threads)
        uint4* Au = (uint4*)Amem;
        #pragma unroll
        for (int i = tid; i < A_BYTES / 16; i += 256)
            Au[i] = make_uint4(0u, 0u, 0u, 0u);
        __syncthreads();

        // metadata: first 128 threads, one edge slot each
        if (tid < TILE_E) {
            int src = 0;
            if (tid < tlen) {
                const int idx = t0 + tid;
                src = esrc[idx];
                const float w = ew[idx];
                const int row = edst[idx] - base_node;   // in [0,16)
                Amem[row * SPAD + tid] = __float2half(w);
            }
            sSrc[tid] = src;
        }
        __syncthreads();

        // gather 128 rows: 16 rows per pass, 16 lanes (uint4) per row
        {
            const int rsub = tid >> 4;      // 0..15
            const int l16  = tid & 15;      // 0..15
            #pragma unroll
            for (int i = 0; i < TILE_E / 16; i++) {
                const int row = i * 16 + rsub;
                const int src = sSrc[row];
                const uint4 v = supv[(size_t)src * 16 + l16];
                *(uint4*)(Smem + row * SPAD + l16 * 8) = v;
            }
        }
        __syncthreads();

        // MMA: acc(16 x 16 cols at n0) += A(16 x 128) @ S(128 x [n0..n0+16))
        #pragma unroll
        for (int ks = 0; ks < TILE_E / 16; ks++) {
            const int k0 = ks * 16;
            const unsigned a0 = *(const unsigned*)(Amem + g * SPAD + k0 + 2 * tig);
            const unsigned a1 = *(const unsigned*)(Amem + (g + 8) * SPAD + k0 + 2 * tig);
            const unsigned a2 = *(const unsigned*)(Amem + g * SPAD + k0 + 8 + 2 * tig);
            const unsigned a3 = *(const unsigned*)(Amem + (g + 8) * SPAD + k0 + 8 + 2 * tig);
            unsigned b0, b1, b2, b3;
            ldsm_x4_trans(b0, b1, b2, b3,
                          Sbase_u32 + (unsigned)((k0 + krow_off) * SPAD + n0 + ncol_off) * 2u);
            mma_f16(acc[0], a0, a1, a2, a3, b0, b1);
            mma_f16(acc[1], a0, a1, a2, a3, b2, b3);
        }
    }

    // epilogue: warp stores its 16x16 slice (zero-edge groups store zeros)
    const int r0 = base_node + (lane >> 2);
    const int r1 = r0 + 8;
    #pragma unroll
    for (int t = 0; t < 2; t++) {
        const int col = n0 + t * 8 + 2 * (lane & 3);
        if (r0 < N)
            *(float2*)(out + (size_t)r0 * D + col) = make_float2(acc[t][0], acc[t][1]);
        if (r1 < N)
            *(float2*)(out + (size_t)r1 * D + col) = make_float2(acc[t][2], acc[t][3]);
    }
}

extern "C" void kernel_launch(void* const* d_in, const int* in_sizes, int n_in,
                              void* d_out, int out_size) {
    const float* x    = (const float*)d_in[0];
    const float* W    = (const float*)d_in[1];
    const float* b    = (const float*)d_in[2];
    const float* ew   = (const float*)d_in[3];
    const int*   esrc = (const int*)d_in[4];
    const int*   edst = (const int*)d_in[5];
    float* out = (float*)d_out;

    const int N = in_sizes[0] / D;
    const int E = in_sizes[3];

    __half* sup = nullptr;
    cudaGetSymbolAddress((void**)&sup, g_support_h);
    __half* Wt = nullptr;
    cudaGetSymbolAddress((void**)&Wt, g_Wt_h);
    int* rp = nullptr;
    cudaGetSymbolAddress((void**)&rp, g_rowptr);

    prep_kernel<<<(D * D + 255) / 256, 256>>>(W, Wt);
    rowptr_kernel<<<(E + 255) / 256, 256>>>(edst, rp, E, N);

    const int gemm_smem = (MBLK * PADH + D * PADH) * (int)sizeof(__half); // ~52 KB
    cudaFuncSetAttribute(gemm_mma_kernel, cudaFuncAttributeMaxDynamicSharedMemorySize, gemm_smem);

    const int gemm_blocks = (N + MBLK - 1) / MBLK;
    gemm_mma_kernel<<<gemm_blocks, 256, gemm_smem>>>(x, Wt, b, sup, N);

    // one block per 16-node group
    const int ngroups = (N + 15) / 16;
    cudaFuncSetAttribute(scatter_mma_kernel, cudaFuncAttributeMaxDynamicSharedMemorySize, SCAT_SMEM);
    scatter_mma_kernel<<<ngroups, 256, SCAT_SMEM>>>(sup, ew, esrc, edst, rp, out, N);
}

// round 17
// speedup vs baseline: 1.7269x; 1.7269x over previous
#include <cuda_runtime.h>
#include <cuda_fp16.h>

#define D 128
#define MAX_N 100000
#define MAX_E 3200000
#define MBLK 64            // rows of x per GEMM block
#define PADH 136           // smem row stride in halves

// support = x@W + b, stored fp16 (25.6 MB)
__device__ __half g_support_h[(size_t)MAX_N * D];
// W transposed + converted to fp16: Wt[n][k]
__device__ __half g_Wt_h[D * D];
// CSR row pointers for destination nodes
__device__ int g_rowptr[MAX_N + 1];
// packed per-edge metadata: (src, w as half2 bits) — one LDG.64 per edge
__device__ int2 g_pack[MAX_E];

// ---------------------------------------------------------------------------
// prep: Wt_h[n][k] = fp16(W[k][n])
// ---------------------------------------------------------------------------
__global__ void prep_kernel(const float* __restrict__ W, __half* __restrict__ Wt) {
    int i = blockIdx.x * blockDim.x + threadIdx.x;
    if (i < D * D) {
        int k = i >> 7, n = i & 127;
        Wt[n * D + k] = __float2half(W[i]);
    }
}

// ---------------------------------------------------------------------------
// edge prep: rowptr (edst sorted) + packed (src, half2(w)) metadata.
// ---------------------------------------------------------------------------
__global__ void edge_prep_kernel(const int* __restrict__ edst,
                                 const int* __restrict__ esrc,
                                 const float* __restrict__ ew,
                                 int* __restrict__ rp,
                                 int2* __restrict__ pk, int E, int N) {
    int e = blockIdx.x * blockDim.x + threadIdx.x;
    if (e >= E) return;
    __half2 h = __float2half2_rn(ew[e]);
    pk[e] = make_int2(esrc[e], *(int*)&h);
    int d  = edst[e];
    int dp = (e == 0) ? -1 : edst[e - 1];
    for (int k = dp + 1; k <= d; k++) rp[k] = e;
    if (e == E - 1)
        for (int k = d + 1; k <= N; k++) rp[k] = E;
}

__device__ __forceinline__ void mma_f16(float d[4], unsigned a0, unsigned a1,
                                        unsigned a2, unsigned a3,
                                        unsigned b0, unsigned b1) {
    asm volatile(
        "mma.sync.aligned.m16n8k16.row.col.f32.f16.f16.f32 "
        "{%0,%1,%2,%3}, {%4,%5,%6,%7}, {%8,%9}, {%0,%1,%2,%3};"
        : "+f"(d[0]), "+f"(d[1]), "+f"(d[2]), "+f"(d[3])
        : "r"(a0), "r"(a1), "r"(a2), "r"(a3), "r"(b0), "r"(b1));
}

// ---------------------------------------------------------------------------
// GEMM: support = fp16(x@W + b) via fp16 mma m16n8k16. (Proven champion.)
// ---------------------------------------------------------------------------
__global__ void __launch_bounds__(256) gemm_mma_kernel(
        const float* __restrict__ x,
        const __half* __restrict__ Wt,
        const float* __restrict__ b,
        __half* __restrict__ sup, int N) {
    extern __shared__ __half smem[];
    __half* sX = smem;                 // 64  x PADH halves
    __half* sW = smem + MBLK * PADH;   // 128 x PADH halves ([n][k])

    const int tid  = threadIdx.x;
    const int lane = tid & 31;
    const int w    = tid >> 5;
    const int wm   = w & 3;
    const int wn   = w >> 2;
    const int g    = lane >> 2;
    const int tig  = lane & 3;

    const int row0 = blockIdx.x * MBLK;

    const uint4* Wv = (const uint4*)Wt;
    #pragma unroll
    for (int i = tid; i < 128 * 16; i += 256) {
        int r = i >> 4, c = i & 15;
        *(uint4*)(sW + r * PADH + c * 8) = Wv[i];
    }
    const float4* xv = (const float4*)x;
    #pragma unroll
    for (int i = tid; i < MBLK * 32; i += 256) {
        int r = i >> 5, c = i & 31;
        float4 v = make_float4(0.f, 0.f, 0.f, 0.f);
        if (row0 + r < N) v = xv[(size_t)(row0 + r) * 32 + c];
        __half2 h0 = __floats2half2_rn(v.x, v.y);
        __half2 h1 = __floats2half2_rn(v.z, v.w);
        uint2 p = make_uint2(*(unsigned*)&h0, *(unsigned*)&h1);
        *(uint2*)(sX + r * PADH + c * 4) = p;
    }
    __syncthreads();

    float acc[8][4];
    #pragma unroll
    for (int t = 0; t < 8; t++)
        #pragma unroll
        for (int j = 0; j < 4; j++) acc[t][j] = 0.f;

    const int ar0 = wm * 16 + g;
    const int ar1 = ar0 + 8;

    #pragma unroll
    for (int k0 = 0; k0 < D; k0 += 16) {
        unsigned a0 = *(const unsigned*)(sX + ar0 * PADH + k0 + 2 * tig);
        unsigned a1 = *(const unsigned*)(sX + ar1 * PADH + k0 + 2 * tig);
        unsigned a2 = *(const unsigned*)(sX + ar0 * PADH + k0 + 2 * tig + 8);
        unsigned a3 = *(const unsigned*)(sX + ar1 * PADH + k0 + 2 * tig + 8);
        #pragma unroll
        for (int t = 0; t < 8; t++) {
            int n0 = wn * 64 + t * 8;
            unsigned b0 = *(const unsigned*)(sW + (n0 + g) * PADH + k0 + 2 * tig);
            unsigned b1 = *(const unsigned*)(sW + (n0 + g) * PADH + k0 + 2 * tig + 8);
            mma_f16(acc[t], a0, a1, a2, a3, b0, b1);
        }
    }

    const int gr0 = row0 + wm * 16 + g;
    const int gr1 = gr0 + 8;
    #pragma unroll
    for (int t = 0; t < 8; t++) {
        int col = wn * 64 + t * 8 + 2 * tig;
        float bx = b[col], by = b[col + 1];
        if (gr0 < N) {
            __half2 h = __floats2half2_rn(acc[t][0] + bx, acc[t][1] + by);
            *(__half2*)(sup + (size_t)gr0 * D + col) = h;
        }
        if (gr1 < N) {
            __half2 h = __floats2half2_rn(acc[t][2] + bx, acc[t][3] + by);
            *(__half2*)(sup + (size_t)gr1 * D + col) = h;
        }
    }
}

// ---------------------------------------------------------------------------
// CSR pull: one warp per destination node (champion structure). fp16
// accumulator blocks: 4 edges accumulated with HFMA2 in half2, flushed to
// fp32 between blocks. Metadata = one LDG.64 (src + pre-converted half2 w).
// No shfl, no atomics; one STG.128 per lane per node.
// ---------------------------------------------------------------------------
__global__ void __launch_bounds__(256) scatter_csr_kernel(
        const __half* __restrict__ sup,
        const int2* __restrict__ pk,
        const int* __restrict__ rp,
        float* __restrict__ out, int N) {
    const int warp = (blockIdx.x * blockDim.x + threadIdx.x) >> 5;
    const int lane = threadIdx.x & 31;
    if (warp >= N) return;

    const int beg = rp[warp];
    const int end = rp[warp + 1];

    const uint2* supv = (const uint2*)sup;
    const __half2 z2 = __float2half2_rn(0.f);
    float4 facc = make_float4(0.f, 0.f, 0.f, 0.f);

    int e = beg;
    #pragma unroll 2
    for (; e + 4 <= end; e += 4) {
        __half2 a01 = z2, a23 = z2;
        #pragma unroll
        for (int j = 0; j < 4; j++) {
            const int2 p = __ldg(pk + e + j);                 // LDG.64, 8B-aligned
            const uint2 u = supv[(size_t)p.x * 32 + lane];    // LDG.64 gather
            const __half2 w2 = *(const __half2*)&p.y;
            a01 = __hfma2(*(const __half2*)&u.x, w2, a01);
            a23 = __hfma2(*(const __half2*)&u.y, w2, a23);
        }
        const float2 f0 = __half22float2(a01);
        const float2 f1 = __half22float2(a23);
        facc.x += f0.x; facc.y += f0.y;
        facc.z += f1.x; facc.w += f1.y;
    }
    if (e < end) {                       // tail: 1-3 edges
        __half2 a01 = z2, a23 = z2;
        for (; e < end; e++) {
            const int2 p = __ldg(pk + e);
            const uint2 u = supv[(size_t)p.x * 32 + lane];
            const __half2 w2 = *(const __half2*)&p.y;
            a01 = __hfma2(*(const __half2*)&u.x, w2, a01);
            a23 = __hfma2(*(const __half2*)&u.y, w2, a23);
        }
        const float2 f0 = __half22float2(a01);
        const float2 f1 = __half22float2(a23);
        facc.x += f0.x; facc.y += f0.y;
        facc.z += f1.x; facc.w += f1.y;
    }

    *(float4*)(out + (size_t)warp * D + lane * 4) = facc;
}

extern "C" void kernel_launch(void* const* d_in, const int* in_sizes, int n_in,
                              void* d_out, int out_size) {
    const float* x    = (const float*)d_in[0];
    const float* W    = (const float*)d_in[1];
    const float* b    = (const float*)d_in[2];
    const float* ew   = (const float*)d_in[3];
    const int*   esrc = (const int*)d_in[4];
    const int*   edst = (const int*)d_in[5];
    float* out = (float*)d_out;

    const int N = in_sizes[0] / D;
    const int E = in_sizes[3];

    __half* sup = nullptr;
    cudaGetSymbolAddress((void**)&sup, g_support_h);
    __half* Wt = nullptr;
    cudaGetSymbolAddress((void**)&Wt, g_Wt_h);
    int* rp = nullptr;
    cudaGetSymbolAddress((void**)&rp, g_rowptr);
    int2* pk = nullptr;
    cudaGetSymbolAddress((void**)&pk, g_pack);

    prep_kernel<<<(D * D + 255) / 256, 256>>>(W, Wt);
    edge_prep_kernel<<<(E + 255) / 256, 256>>>(edst, esrc, ew, rp, pk, E, N);

    const int gemm_smem = (MBLK * PADH + D * PADH) * (int)sizeof(__half); // ~52 KB
    cudaFuncSetAttribute(gemm_mma_kernel, cudaFuncAttributeMaxDynamicSharedMemorySize, gemm_smem);

    const int gemm_blocks = (N + MBLK - 1) / MBLK;
    gemm_mma_kernel<<<gemm_blocks, 256, gemm_smem>>>(x, Wt, b, sup, N);

    // one warp per node, 8 warps per block
    const int scat_blocks = (N + 7) / 8;
    scatter_csr_kernel<<<scat_blocks, 256>>>(sup, pk, rp, out, N);
}